// round 6
// baseline (speedup 1.0000x reference)
#include <cuda_runtime.h>

// TrajectoryPredictor: 2-layer LSTM encoder (T=15) + 10-step LSTM decoder with
// LayerNorm + Gaussian heads. B=65536, H=128, IN=6, OUT=3.
//
// Persistent-CTA design: each CTA owns BB=64 batch rows, keeps all recurrent
// state in shared memory, runs all 15+10 steps locally. Weights pre-transposed
// (k-major) into __device__ scratch; staged per-16k-tile into shared with a
// register-prefetch pipeline. Inner product uses fma.rn.f32x2 (packed fp32
// pair FMA). 8 warps, each warp owns 8 batch rows x all 512 gate columns so
// weight LDS traffic is 64 B/cyc (half the crossbar cap) and the fma2 pipe is
// the sole limiter.

#define NBATCH 65536
#define TSTEPS 15
#define HDIM   128
#define NIN    6
#define NOUT   3
#define HOR    10
#define G4     512      // 4*H gates
#define BB     64       // batch rows per CTA
#define NT     256      // threads per CTA (8 warps x 8 rows)
#define KT     16       // k-tile for weight staging

#define K0TOT  144      // layer0 unified K: 128 (h) + 6 (x) + 10 pad
#define LD0    144      // h0x row stride (576B, 16B aligned)
#define KCAT   144      // decoder cat K: 3 (prev) + 128 (emb) + 13 pad

typedef unsigned long long u64;

// ---------------- transposed weight scratch (device globals, no allocs) ------
__device__ float g_WT0  [K0TOT * G4];   // rows 0..127 Whh0^T, 128..133 Wih0^T, rest 0
__device__ float g_WTih1[HDIM * G4];
__device__ float g_WThh1[HDIM * G4];
__device__ float g_WTihd[HDIM * G4];
__device__ float g_WThhd[HDIM * G4];
__device__ float g_WTp  [KCAT * HDIM];  // rows 0..130 Wp^T, rest 0

__global__ void prep_kernel(const float* __restrict__ Wih0, const float* __restrict__ Whh0,
                            const float* __restrict__ Wih1, const float* __restrict__ Whh1,
                            const float* __restrict__ Wihd, const float* __restrict__ Whhd,
                            const float* __restrict__ Wp)
{
    int idx = blockIdx.x * blockDim.x + threadIdx.x;
    if (idx < K0TOT * G4) {
        int k = idx >> 9, g = idx & 511;
        float v = 0.f;
        if (k < 128)      v = Whh0[g * 128 + k];
        else if (k < 134) v = Wih0[g * 6 + (k - 128)];
        g_WT0[idx] = v;
    }
    int i2 = idx - K0TOT * G4;
    if (i2 >= 0 && i2 < HDIM * G4) {
        int k = i2 >> 9, g = i2 & 511;
        g_WTih1[i2] = Wih1[g * 128 + k];
        g_WThh1[i2] = Whh1[g * 128 + k];
        g_WTihd[i2] = Wihd[g * 128 + k];
        g_WThhd[i2] = Whhd[g * 128 + k];
    }
    int i3 = i2 - HDIM * G4;
    if (i3 >= 0 && i3 < KCAT * HDIM) {
        int k = i3 >> 7, j = i3 & 127;
        g_WTp[i3] = (k < 131) ? Wp[j * 131 + k] : 0.f;
    }
}

// ---------------- packed fp32x2 helpers --------------------------------------
__device__ __forceinline__ u64 dup2(float x) {
    u64 r; asm("mov.b64 %0, {%1, %1};" : "=l"(r) : "f"(x)); return r;
}
__device__ __forceinline__ void fma2(u64& d, u64 a, u64 b) {
    asm("fma.rn.f32x2 %0, %1, %2, %0;" : "+l"(d) : "l"(a), "l"(b));
}
__device__ __forceinline__ float2 unp(u64 v) {
    float lo, hi; asm("mov.b64 {%0, %1}, %2;" : "=f"(lo), "=f"(hi) : "l"(v));
    return make_float2(lo, hi);
}
__device__ __forceinline__ float sigf(float x)  { return __fdividef(1.f, 1.f + __expf(-x)); }
__device__ __forceinline__ float tanha(float x) { return 2.f * sigf(2.f * x) - 1.f; }

// ---------------- GEMM into 512 gate columns (pipelined weight staging) ------
// Warp w owns rows w*8..w*8+7. acc[(rr*4+G)*2+p] holds gate pre-activation for
// (row = w*8+rr, col = G*128 + tx*4 + 2p + {0,1}). K must be a multiple of 16.
__device__ __forceinline__ void gemm512(u64* acc, const float* __restrict__ WT,
                                        const float* sop, int ldo, int K,
                                        float* wbuf, int tid)
{
    int tx = tid & 31, wp = tid >> 5;
    const float* oprow = sop + (wp * 8) * ldo;
    int ntiles = K >> 4;
    float4 pf[8];
    {
        const float4* src = (const float4*)WT;
#pragma unroll
        for (int j = 0; j < 8; j++) pf[j] = src[tid + j * NT];
    }
    for (int t = 0; t < ntiles; t++) {
        __syncthreads();                     // previous wbuf consumers done
        {
            float4* dst = (float4*)wbuf;
#pragma unroll
            for (int j = 0; j < 8; j++) dst[tid + j * NT] = pf[j];
        }
        if (t + 1 < ntiles) {                // prefetch next tile (hidden by compute)
            const float4* src = (const float4*)(WT + (t + 1) * KT * G4);
#pragma unroll
            for (int j = 0; j < 8; j++) pf[j] = src[tid + j * NT];
        }
        __syncthreads();
        int k0 = t * KT;
#pragma unroll
        for (int k = 0; k < KT; k++) {
            float h8[8];
#pragma unroll
            for (int rr = 0; rr < 8; rr++) h8[rr] = oprow[rr * ldo + k0 + k];
            const float* wrow = wbuf + k * G4 + tx * 4;
            ulonglong2 w0 = *(const ulonglong2*)(wrow);
            ulonglong2 w1 = *(const ulonglong2*)(wrow + 128);
            ulonglong2 w2 = *(const ulonglong2*)(wrow + 256);
            ulonglong2 w3 = *(const ulonglong2*)(wrow + 384);
#pragma unroll
            for (int rr = 0; rr < 8; rr++) {
                u64 hd = dup2(h8[rr]);
                fma2(acc[(rr * 4 + 0) * 2 + 0], hd, w0.x);
                fma2(acc[(rr * 4 + 0) * 2 + 1], hd, w0.y);
                fma2(acc[(rr * 4 + 1) * 2 + 0], hd, w1.x);
                fma2(acc[(rr * 4 + 1) * 2 + 1], hd, w1.y);
                fma2(acc[(rr * 4 + 2) * 2 + 0], hd, w2.x);
                fma2(acc[(rr * 4 + 2) * 2 + 1], hd, w2.y);
                fma2(acc[(rr * 4 + 3) * 2 + 0], hd, w3.x);
                fma2(acc[(rr * 4 + 3) * 2 + 1], hd, w3.y);
            }
        }
    }
}

// ---------------- GEMM into 128 columns (decoder pre-projection) -------------
// Warp w owns rows w*8..w*8+7. acc[rr*2+p]: (row = w*8+rr, col = tx*4+2p+{0,1})
__device__ __forceinline__ void gemm128(u64* acc, const float* __restrict__ WT,
                                        const float* sop, int ldo, int K,
                                        float* wbuf, int tid)
{
    int tx = tid & 31, wp = tid >> 5;
    const float* oprow = sop + (wp * 8) * ldo;
    int ntiles = K >> 4;
    float4 pf[2];
    {
        const float4* src = (const float4*)WT;
#pragma unroll
        for (int j = 0; j < 2; j++) pf[j] = src[tid + j * NT];
    }
    for (int t = 0; t < ntiles; t++) {
        __syncthreads();
        {
            float4* dst = (float4*)wbuf;
#pragma unroll
            for (int j = 0; j < 2; j++) dst[tid + j * NT] = pf[j];
        }
        if (t + 1 < ntiles) {
            const float4* src = (const float4*)(WT + (t + 1) * KT * HDIM);
#pragma unroll
            for (int j = 0; j < 2; j++) pf[j] = src[tid + j * NT];
        }
        __syncthreads();
        int k0 = t * KT;
#pragma unroll
        for (int k = 0; k < KT; k++) {
            float h8[8];
#pragma unroll
            for (int rr = 0; rr < 8; rr++) h8[rr] = oprow[rr * ldo + k0 + k];
            ulonglong2 w = *(const ulonglong2*)(wbuf + k * HDIM + tx * 4);
#pragma unroll
            for (int rr = 0; rr < 8; rr++) {
                u64 hd = dup2(h8[rr]);
                fma2(acc[rr * 2 + 0], hd, w.x);
                fma2(acc[rr * 2 + 1], hd, w.y);
            }
        }
    }
}

// ---------------- LSTM cell update (thread-local gates) ----------------------
// bias lives in shared (sbias, 512 floats).
__device__ __forceinline__ void lstm_update(u64* acc, const float* sbias,
                                            float* sC, float* sH, int ldh, int tid)
{
    int tx = tid & 31, wp = tid >> 5;
    int jb = tx * 4;
    float barr[4][4];
#pragma unroll
    for (int G = 0; G < 4; G++) {
        float4 bv = *(const float4*)(sbias + G * 128 + jb);
        barr[G][0] = bv.x; barr[G][1] = bv.y; barr[G][2] = bv.z; barr[G][3] = bv.w;
    }
    __syncthreads();   // all GEMM readers of old h done before we overwrite h
#pragma unroll
    for (int rr = 0; rr < 8; rr++) {
        int row = wp * 8 + rr;
        float4 c4 = *(float4*)(sC + row * 128 + jb);
        float cc[4] = {c4.x, c4.y, c4.z, c4.w};
        float gv[4][4];
#pragma unroll
        for (int G = 0; G < 4; G++) {
            float2 a  = unp(acc[(rr * 4 + G) * 2 + 0]);
            float2 b2 = unp(acc[(rr * 4 + G) * 2 + 1]);
            gv[G][0] = a.x; gv[G][1] = a.y; gv[G][2] = b2.x; gv[G][3] = b2.y;
        }
        float co[4], ho[4];
#pragma unroll
        for (int jj = 0; jj < 4; jj++) {
            float i_ = sigf (gv[0][jj] + barr[0][jj]);
            float f_ = sigf (gv[1][jj] + barr[1][jj]);
            float g_ = tanha(gv[2][jj] + barr[2][jj]);
            float o_ = sigf (gv[3][jj] + barr[3][jj]);
            float cn = f_ * cc[jj] + i_ * g_;
            co[jj] = cn;
            ho[jj] = o_ * tanha(cn);
        }
        *(float4*)(sC + row * 128 + jb) = make_float4(co[0], co[1], co[2], co[3]);
        *(float4*)(sH + row * ldh + jb) = make_float4(ho[0], ho[1], ho[2], ho[3]);
    }
}

// ---------------- shared memory layout (floats) ------------------------------
#define OFF_H0X 0                         // 64 x 144  (h0 + x_t in cols 128..133)
#define OFF_C0  (OFF_H0X + BB * LD0)      // 64 x 128
#define OFF_H1  (OFF_C0 + BB * HDIM)      // 64 x 128
#define OFF_C1  (OFF_H1 + BB * HDIM)      // 64 x 128
#define OFF_UN  (OFF_C1 + BB * HDIM)      // 64 x 144 (x tile 64x90, then cat)
#define OFF_WB  (OFF_UN + BB * KCAT)      // KT x 512 weight stage
#define OFF_EMB (OFF_WB + KT * G4)        // 11 x 128
#define OFF_PRE (OFF_EMB + 11 * HDIM)     // 64 x 4
#define OFF_WM  (OFF_PRE + BB * 4)        // 3 x 128
#define OFF_WS  (OFF_WM + 3 * HDIM)       // 3 x 128
#define OFF_LG  (OFF_WS + 3 * HDIM)       // 128
#define OFF_LB  (OFF_LG + HDIM)           // 128
#define OFF_B0  (OFF_LB + HDIM)           // 512
#define OFF_B1  (OFF_B0 + G4)             // 512
#define OFF_BD  (OFF_B1 + G4)             // 512
#define OFF_BP  (OFF_BD + G4)             // 128
#define OFF_BMS (OFF_BP + HDIM)           // 8 (bm[3], bs[3])
#define SMEM_FLOATS (OFF_BMS + 8)
#define SMEM_BYTES  (SMEM_FLOATS * 4)

extern __shared__ float smem[];

__global__ void __launch_bounds__(NT, 1)
traj_kernel(const float* __restrict__ x,
            const float* __restrict__ b0, const float* __restrict__ b1,
            const float* __restrict__ bd, const float* __restrict__ emb,
            const float* __restrict__ bp, const float* __restrict__ Wm,
            const float* __restrict__ bm, const float* __restrict__ Ws,
            const float* __restrict__ bs, const float* __restrict__ lng,
            const float* __restrict__ lnb, float* __restrict__ out)
{
    float* h0x  = smem + OFF_H0X;
    float* c0   = smem + OFF_C0;
    float* h1   = smem + OFF_H1;
    float* c1   = smem + OFF_C1;
    float* un   = smem + OFF_UN;
    float* wbuf = smem + OFF_WB;
    float* semb = smem + OFF_EMB;
    float* sprev= smem + OFF_PRE;
    float* sWm  = smem + OFF_WM;
    float* sWs  = smem + OFF_WS;
    float* slng = smem + OFF_LG;
    float* slnb = smem + OFF_LB;
    float* sb0  = smem + OFF_B0;
    float* sb1  = smem + OFF_B1;
    float* sbd  = smem + OFF_BD;
    float* sbp  = smem + OFF_BP;
    float* sbms = smem + OFF_BMS;

    int tid = threadIdx.x;
    int bbase = blockIdx.x * BB;

    // ---- init: zero states, load x tile / emb / biases / head params --------
    for (int i = tid; i < BB * LD0; i += NT) h0x[i] = 0.f;
    for (int i = tid; i < BB * HDIM; i += NT) { c0[i] = 0.f; h1[i] = 0.f; c1[i] = 0.f; }
    for (int i = tid; i < BB * TSTEPS * NIN; i += NT) un[i] = x[(size_t)bbase * TSTEPS * NIN + i];
    for (int i = tid; i < 11 * HDIM; i += NT) semb[i] = emb[i];
    for (int i = tid; i < 3 * HDIM; i += NT) { sWm[i] = Wm[i]; sWs[i] = Ws[i]; }
    for (int i = tid; i < HDIM; i += NT) { slng[i] = lng[i]; slnb[i] = lnb[i]; sbp[i] = bp[i]; }
    for (int i = tid; i < G4; i += NT) { sb0[i] = b0[i]; sb1[i] = b1[i]; sbd[i] = bd[i]; }
    if (tid < 3) { sbms[tid] = bm[tid]; sbms[4 + tid] = bs[tid]; }
    // (first gemm's double sync makes all init visible before any compute)

    u64 acc[64];

    // ---- encoder: fused layer0 + layer1, step by step -----------------------
    for (int t = 0; t < TSTEPS; t++) {
        for (int i = tid; i < BB * NIN; i += NT) {
            int r = i / NIN, k = i - r * NIN;
            h0x[r * LD0 + 128 + k] = un[r * (TSTEPS * NIN) + t * NIN + k];
        }
#pragma unroll
        for (int i = 0; i < 64; i++) acc[i] = 0ull;
        gemm512(acc, g_WT0, h0x, LD0, K0TOT, wbuf, tid);       // h-part + x-part fused
        lstm_update(acc, sb0, c0, h0x, LD0, tid);              // h0 := out0[t]

#pragma unroll
        for (int i = 0; i < 64; i++) acc[i] = 0ull;
        gemm512(acc, g_WTih1, h0x, LD0, HDIM, wbuf, tid);
        gemm512(acc, g_WThh1, h1, HDIM, HDIM, wbuf, tid);
        lstm_update(acc, sb1, c1, h1, HDIM, tid);
    }

    // prev0 = x[:, -1, :3]
    for (int i = tid; i < BB * NOUT; i += NT) {
        int r = i / NOUT, o = i - r * NOUT;
        sprev[r * 4 + o] = un[r * (TSTEPS * NIN) + 14 * NIN + o];
    }
    __syncthreads();

    // ---- decoder ------------------------------------------------------------
    for (int s = 0; s < HOR; s++) {
        __syncthreads();   // prev writes (LN phase) + previous cat readers done
        for (int i = tid; i < BB * KCAT; i += NT) {
            int r = i / KCAT, k = i - r * KCAT;
            float v = 0.f;
            if (k < 3)        v = sprev[r * 4 + k];
            else if (k < 131) v = semb[s * HDIM + (k - 3)];
            un[i] = v;
        }

        u64 acc16[16];
#pragma unroll
        for (int i = 0; i < 16; i++) acc16[i] = 0ull;
        gemm128(acc16, g_WTp, un, KCAT, KCAT, wbuf, tid);
        {   // dec_in = relu(cat @ Wp^T + bp) -> h0x cols 0..127
            int tx = tid & 31, wp = tid >> 5;
            float4 bv = *(const float4*)(sbp + tx * 4);
            float bb4[4] = {bv.x, bv.y, bv.z, bv.w};
#pragma unroll
            for (int rr = 0; rr < 8; rr++) {
                float2 a  = unp(acc16[rr * 2 + 0]);
                float2 b2 = unp(acc16[rr * 2 + 1]);
                float v0 = fmaxf(a.x  + bb4[0], 0.f);
                float v1 = fmaxf(a.y  + bb4[1], 0.f);
                float v2 = fmaxf(b2.x + bb4[2], 0.f);
                float v3 = fmaxf(b2.y + bb4[3], 0.f);
                *(float4*)(h0x + (wp * 8 + rr) * LD0 + tx * 4) = make_float4(v0, v1, v2, v3);
            }
        }

#pragma unroll
        for (int i = 0; i < 64; i++) acc[i] = 0ull;
        gemm512(acc, g_WTihd, h0x, LD0, HDIM, wbuf, tid);
        gemm512(acc, g_WThhd, h1, HDIM, HDIM, wbuf, tid);
        lstm_update(acc, sbd, c1, h1, HDIM, tid);
        __syncthreads();   // h1 (h_dec) visible for LN/head phase

        {   // LayerNorm + heads: 4 threads per row, 32 elems each
            int row = tid >> 2, sub = tid & 3;
            const float* hr = h1 + row * HDIM + sub * 32;
            float hv[32];
#pragma unroll
            for (int q = 0; q < 8; q++) {
                float4 v = *(const float4*)(hr + q * 4);
                hv[q*4+0] = v.x; hv[q*4+1] = v.y; hv[q*4+2] = v.z; hv[q*4+3] = v.w;
            }
            float s1 = 0.f, s2 = 0.f;
#pragma unroll
            for (int q = 0; q < 32; q++) { s1 += hv[q]; s2 += hv[q] * hv[q]; }
#pragma unroll
            for (int d = 1; d < 4; d <<= 1) {
                s1 += __shfl_xor_sync(0xffffffffu, s1, d);
                s2 += __shfl_xor_sync(0xffffffffu, s2, d);
            }
            float mean = s1 * (1.f / 128.f);
            float var  = s2 * (1.f / 128.f) - mean * mean;
            float rstd = rsqrtf(var + 1e-5f);
            float m0 = 0, m1 = 0, m2 = 0, t0 = 0, t1 = 0, t2 = 0;
#pragma unroll
            for (int q = 0; q < 32; q++) {
                int j = sub * 32 + q;
                float f = (hv[q] - mean) * rstd * slng[j] + slnb[j];
                m0 += f * sWm[j];       m1 += f * sWm[128 + j]; m2 += f * sWm[256 + j];
                t0 += f * sWs[j];       t1 += f * sWs[128 + j]; t2 += f * sWs[256 + j];
            }
#pragma unroll
            for (int d = 1; d < 4; d <<= 1) {
                m0 += __shfl_xor_sync(0xffffffffu, m0, d);
                m1 += __shfl_xor_sync(0xffffffffu, m1, d);
                m2 += __shfl_xor_sync(0xffffffffu, m2, d);
                t0 += __shfl_xor_sync(0xffffffffu, t0, d);
                t1 += __shfl_xor_sync(0xffffffffu, t1, d);
                t2 += __shfl_xor_sync(0xffffffffu, t2, d);
            }
            if (sub == 0) {
                int gb = bbase + row;
                float mu0 = m0 + sbms[0], mu1 = m1 + sbms[1], mu2 = m2 + sbms[2];
                float l0 = fminf(fmaxf(t0 + sbms[4], -6.f), 3.f);
                float l1 = fminf(fmaxf(t1 + sbms[5], -6.f), 3.f);
                float l2 = fminf(fmaxf(t2 + sbms[6], -6.f), 3.f);
                size_t base = ((size_t)gb * HOR + s) * NOUT;
                out[base + 0] = mu0; out[base + 1] = mu1; out[base + 2] = mu2;
                float* outs = out + (size_t)NBATCH * HOR * NOUT;
                outs[base + 0] = l0; outs[base + 1] = l1; outs[base + 2] = l2;
                sprev[row * 4 + 0] = mu0; sprev[row * 4 + 1] = mu1; sprev[row * 4 + 2] = mu2;
            }
        }
    }
}

extern "C" void kernel_launch(void* const* d_in, const int* in_sizes, int n_in,
                              void* d_out, int out_size)
{
    const float* x    = (const float*)d_in[0];
    const float* Wih0 = (const float*)d_in[1];
    const float* Whh0 = (const float*)d_in[2];
    const float* b0   = (const float*)d_in[3];
    const float* Wih1 = (const float*)d_in[4];
    const float* Whh1 = (const float*)d_in[5];
    const float* b1   = (const float*)d_in[6];
    const float* Wihd = (const float*)d_in[7];
    const float* Whhd = (const float*)d_in[8];
    const float* bd   = (const float*)d_in[9];
    const float* emb  = (const float*)d_in[10];
    const float* Wp   = (const float*)d_in[11];
    const float* bp   = (const float*)d_in[12];
    const float* Wm   = (const float*)d_in[13];
    const float* bm   = (const float*)d_in[14];
    const float* Ws   = (const float*)d_in[15];
    const float* bs   = (const float*)d_in[16];
    const float* lng  = (const float*)d_in[17];
    const float* lnb  = (const float*)d_in[18];
    float* out = (float*)d_out;

    cudaFuncSetAttribute(traj_kernel, cudaFuncAttributeMaxDynamicSharedMemorySize, SMEM_BYTES);

    int prep_total = K0TOT * G4 + HDIM * G4 + KCAT * HDIM;
    prep_kernel<<<(prep_total + 255) / 256, 256>>>(Wih0, Whh0, Wih1, Whh1, Wihd, Whhd, Wp);

    traj_kernel<<<NBATCH / BB, NT, SMEM_BYTES>>>(x, b0, b1, bd, emb, bp, Wm, bm, Ws, bs,
                                                 lng, lnb, out);
}

// round 14
// speedup vs baseline: 1.0325x; 1.0325x over previous
#include <cuda_runtime.h>

// TrajectoryPredictor: 2-layer LSTM encoder (T=15) + 10-step LSTM decoder with
// LayerNorm + Gaussian heads. B=65536, H=128, IN=6, OUT=3.
//
// Persistent-CTA, column-sliced warps: each CTA owns BB=64 batch rows; each of
// 16 warps owns 32 GATE COLUMNS (all 64 rows), with gates interleaved in the
// weight layout (col = j*4+gate) so each thread holds all 4 gates of one
// hidden unit -> thread-local LSTM cell update. Weights are read from shared
// exactly once per k per SM (2KB/k); activations are stored transposed
// (hT[k][row], stride 68) so the h operand is a broadcast LDS.128.
// Inner product uses fma.rn.f32x2. Decoder pre-projection is closed-form
// (K=3) using a prep-computed emb @ Wp^T table.

#define NBATCH 65536
#define TSTEPS 15
#define HDIM   128
#define NIN    6
#define NOUT   3
#define HOR    10
#define G4     512      // 4*H gate columns
#define BB     64       // batch rows per CTA
#define NT     512      // threads per CTA (16 warps)
#define KT     16       // k-tile for weight staging
#define K0TOT  144      // layer0 unified K: 128 (h) + 6 (x) + 10 pad
#define STRH   68       // hT row stride in floats (16B aligned, bank-skewed)

typedef unsigned long long u64;

// ---------------- prepped weights (device globals, no allocs) ----------------
// Layout: WT[k][j*4+g]  (gate-interleaved columns)
__device__ float g_WT0  [K0TOT * G4];
__device__ float g_WTih1[HDIM * G4];
__device__ float g_WThh1[HDIM * G4];
__device__ float g_WTihd[HDIM * G4];
__device__ float g_WThhd[HDIM * G4];
__device__ float g_embWp[HOR * HDIM];   // emb[s] @ Wp[:,3:]^T
__device__ float g_Wp3  [HDIM * 4];     // Wp[:,0:3] padded to 4

__global__ void prep_kernel(const float* __restrict__ Wih0, const float* __restrict__ Whh0,
                            const float* __restrict__ Wih1, const float* __restrict__ Whh1,
                            const float* __restrict__ Wihd, const float* __restrict__ Whhd,
                            const float* __restrict__ Wp,   const float* __restrict__ emb)
{
    int idx = blockIdx.x * blockDim.x + threadIdx.x;
    if (idx < K0TOT * G4) {
        int k = idx >> 9, c = idx & 511;
        int j = c >> 2, g = c & 3;
        int row = g * 128 + j;
        float v = 0.f;
        if (k < 128)      v = Whh0[row * 128 + k];
        else if (k < 134) v = Wih0[row * 6 + (k - 128)];
        g_WT0[idx] = v;
    }
    int i2 = idx - K0TOT * G4;
    if (i2 >= 0 && i2 < HDIM * G4) {
        int k = i2 >> 9, c = i2 & 511;
        int j = c >> 2, g = c & 3;
        int row = g * 128 + j;
        g_WTih1[i2] = Wih1[row * 128 + k];
        g_WThh1[i2] = Whh1[row * 128 + k];
        g_WTihd[i2] = Wihd[row * 128 + k];
        g_WThhd[i2] = Whhd[row * 128 + k];
    }
    int i3 = i2 - HDIM * G4;
    if (i3 >= 0 && i3 < HOR * HDIM) {
        int s = i3 >> 7, j = i3 & 127;
        float a = 0.f;
        for (int k = 0; k < 128; k++) a += emb[s * 128 + k] * Wp[j * 131 + 3 + k];
        g_embWp[i3] = a;
    }
    int i4 = i3 - HOR * HDIM;
    if (i4 >= 0 && i4 < HDIM * 4) {
        int j = i4 >> 2, k = i4 & 3;
        g_Wp3[i4] = (k < 3) ? Wp[j * 131 + k] : 0.f;
    }
}

// ---------------- packed fp32x2 helpers --------------------------------------
__device__ __forceinline__ u64 dup2(float x) {
    u64 r; asm("mov.b64 %0, {%1, %1};" : "=l"(r) : "f"(x)); return r;
}
__device__ __forceinline__ void fma2(u64& d, u64 a, u64 b) {
    asm("fma.rn.f32x2 %0, %1, %2, %0;" : "+l"(d) : "l"(a), "l"(b));
}
__device__ __forceinline__ float2 unp(u64 v) {
    float lo, hi; asm("mov.b64 {%0, %1}, %2;" : "=f"(lo), "=f"(hi) : "l"(v));
    return make_float2(lo, hi);
}
__device__ __forceinline__ float sigf(float x)  { return __fdividef(1.f, 1.f + __expf(-x)); }
__device__ __forceinline__ float tanha(float x) { return 2.f * sigf(2.f * x) - 1.f; }

// ---------------- GEMM: all 64 rows x 512 gate cols, col-sliced --------------
// Thread (c8 = tid&7, r8 = (tid>>3)&3, w = tid>>5): hidden j = w*8+c8;
// rows b*16 + r8*4 + r for b,r in 0..3. acc[(b*4+r)*2 + {0,1}] = (i,f),(g,o).
// K must be a multiple of 16.
__device__ __forceinline__ void gemm512(u64* acc, const float* __restrict__ WT,
                                        const float* hT, int K,
                                        float* wbuf, int tid)
{
    int c8 = tid & 7, r8 = (tid >> 3) & 3, w = tid >> 5;
    int jg4 = (w * 8 + c8) * 4;
    const float* hbase = hT + r8 * 4;
    int ntiles = K >> 4;
    float4 pf[4];
    {
        const float4* src = (const float4*)WT;
#pragma unroll
        for (int q = 0; q < 4; q++) pf[q] = src[tid + q * NT];
    }
    for (int t = 0; t < ntiles; t++) {
        __syncthreads();                      // previous wbuf consumers done
        {
            float4* dst = (float4*)wbuf;
#pragma unroll
            for (int q = 0; q < 4; q++) dst[tid + q * NT] = pf[q];
        }
        if (t + 1 < ntiles) {                 // prefetch next tile during compute
            const float4* src = (const float4*)(WT + (t + 1) * KT * G4);
#pragma unroll
            for (int q = 0; q < 4; q++) pf[q] = src[tid + q * NT];
        }
        __syncthreads();
        int k0 = t * KT;
#pragma unroll
        for (int k = 0; k < KT; k++) {
            const float* hrow = hbase + (k0 + k) * STRH;
            float4 hb[4];
#pragma unroll
            for (int b = 0; b < 4; b++) hb[b] = *(const float4*)(hrow + b * 16);
            ulonglong2 wv = *(const ulonglong2*)(wbuf + k * G4 + jg4);
#pragma unroll
            for (int b = 0; b < 4; b++) {
#pragma unroll
                for (int r = 0; r < 4; r++) {
                    u64 hd = dup2(((const float*)&hb[b])[r]);
                    fma2(acc[(b * 4 + r) * 2 + 0], hd, wv.x);
                    fma2(acc[(b * 4 + r) * 2 + 1], hd, wv.y);
                }
            }
        }
    }
}

// ---------------- LSTM cell update (thread-local: 1 hidden j x 16 rows) ------
__device__ __forceinline__ void lstm_update(u64* acc, const float* sbias4,
                                            float* cT, float* hT, int tid)
{
    int c8 = tid & 7, r8 = (tid >> 3) & 3, w = tid >> 5;
    int j = w * 8 + c8;
    float4 bv = *(const float4*)(sbias4 + j * 4);   // (bi, bf, bg, bo)
    __syncthreads();   // all gemm reads of old h done before overwrite
#pragma unroll
    for (int b = 0; b < 4; b++) {
        int off = j * STRH + b * 16 + r8 * 4;
        float4 c4 = *(float4*)(cT + off);
        float cc[4] = {c4.x, c4.y, c4.z, c4.w};
        float co[4], ho[4];
#pragma unroll
        for (int r = 0; r < 4; r++) {
            float2 pa = unp(acc[(b * 4 + r) * 2 + 0]);
            float2 pb = unp(acc[(b * 4 + r) * 2 + 1]);
            float i_ = sigf (pa.x + bv.x);
            float f_ = sigf (pa.y + bv.y);
            float g_ = tanha(pb.x + bv.z);
            float o_ = sigf (pb.y + bv.w);
            float cn = f_ * cc[r] + i_ * g_;
            co[r] = cn;
            ho[r] = o_ * tanha(cn);
        }
        *(float4*)(cT + off) = make_float4(co[0], co[1], co[2], co[3]);
        *(float4*)(hT + off) = make_float4(ho[0], ho[1], ho[2], ho[3]);
    }
}

// ---------------- shared memory layout (floats) ------------------------------
#define OFF_H0XT 0                          // 144 x 68 (h0 rows 0..127, x rows 128..133)
#define OFF_C0T  (OFF_H0XT + K0TOT * STRH)  // 128 x 68
#define OFF_H1T  (OFF_C0T + HDIM * STRH)    // 128 x 68
#define OFF_C1T  (OFF_H1T + HDIM * STRH)    // 128 x 68
#define OFF_UN   (OFF_C1T + HDIM * STRH)    // 64 x 90 x tile (row-major)
#define OFF_WB   (OFF_UN + BB * TSTEPS * NIN) // 16 x 512
#define OFF_EWP  (OFF_WB + KT * G4)         // 10 x 128
#define OFF_WP3  (OFF_EWP + HOR * HDIM)     // 128 x 4
#define OFF_PRE  (OFF_WP3 + HDIM * 4)       // 64 x 4
#define OFF_WM   (OFF_PRE + BB * 4)         // 3 x 128
#define OFF_WS   (OFF_WM + 3 * HDIM)        // 3 x 128
#define OFF_LG   (OFF_WS + 3 * HDIM)        // 128
#define OFF_LB   (OFF_LG + HDIM)            // 128
#define OFF_B0   (OFF_LB + HDIM)            // 512 (j*4+g layout)
#define OFF_B1   (OFF_B0 + G4)
#define OFF_BD   (OFF_B1 + G4)
#define OFF_BP   (OFF_BD + G4)              // 128
#define OFF_BMS  (OFF_BP + HDIM)            // 8
#define SMEM_FLOATS (OFF_BMS + 8)
#define SMEM_BYTES  (SMEM_FLOATS * 4)

extern __shared__ float smem[];

__global__ void __launch_bounds__(NT, 1)
traj_kernel(const float* __restrict__ x,
            const float* __restrict__ b0, const float* __restrict__ b1,
            const float* __restrict__ bd,
            const float* __restrict__ bp, const float* __restrict__ Wm,
            const float* __restrict__ bm, const float* __restrict__ Ws,
            const float* __restrict__ bs, const float* __restrict__ lng,
            const float* __restrict__ lnb, float* __restrict__ out)
{
    float* h0xT = smem + OFF_H0XT;
    float* c0T  = smem + OFF_C0T;
    float* h1T  = smem + OFF_H1T;
    float* c1T  = smem + OFF_C1T;
    float* un   = smem + OFF_UN;
    float* wbuf = smem + OFF_WB;
    float* sewp = smem + OFF_EWP;
    float* sWp3 = smem + OFF_WP3;
    float* sprev= smem + OFF_PRE;
    float* sWm  = smem + OFF_WM;
    float* sWs  = smem + OFF_WS;
    float* slng = smem + OFF_LG;
    float* slnb = smem + OFF_LB;
    float* sb0  = smem + OFF_B0;
    float* sb1  = smem + OFF_B1;
    float* sbd  = smem + OFF_BD;
    float* sbp  = smem + OFF_BP;
    float* sbms = smem + OFF_BMS;

    int tid = threadIdx.x;
    int bbase = blockIdx.x * BB;

    // ---- init ---------------------------------------------------------------
    for (int i = tid; i < K0TOT * STRH; i += NT) h0xT[i] = 0.f;
    for (int i = tid; i < HDIM * STRH; i += NT) { c0T[i] = 0.f; h1T[i] = 0.f; c1T[i] = 0.f; }
    for (int i = tid; i < BB * TSTEPS * NIN; i += NT) un[i] = x[(size_t)bbase * TSTEPS * NIN + i];
    for (int i = tid; i < HOR * HDIM; i += NT) sewp[i] = g_embWp[i];
    for (int i = tid; i < HDIM * 4; i += NT) sWp3[i] = g_Wp3[i];
    for (int i = tid; i < 3 * HDIM; i += NT) { sWm[i] = Wm[i]; sWs[i] = Ws[i]; }
    for (int i = tid; i < HDIM; i += NT) { slng[i] = lng[i]; slnb[i] = lnb[i]; sbp[i] = bp[i]; }
    for (int i = tid; i < G4; i += NT) {   // rearrange biases to j*4+g
        int j = i >> 2, g = i & 3;
        sb0[i] = b0[g * 128 + j]; sb1[i] = b1[g * 128 + j]; sbd[i] = bd[g * 128 + j];
    }
    if (tid < 3) { sbms[tid] = bm[tid]; sbms[4 + tid] = bs[tid]; }
    __syncthreads();   // init complete before any reader (incl. x scatter)

    int c8 = tid & 7, r8 = (tid >> 3) & 3, w = tid >> 5;
    int jj = w * 8 + c8;

    u64 acc[32];

    // ---- encoder ------------------------------------------------------------
    for (int t = 0; t < TSTEPS; t++) {
        if (tid < BB * NIN) {   // scatter x_t into h0xT rows 128..133 (transposed)
            int r = tid / NIN, k = tid - r * NIN;
            h0xT[(128 + k) * STRH + r] = un[r * (TSTEPS * NIN) + t * NIN + k];
        }
#pragma unroll
        for (int i = 0; i < 32; i++) acc[i] = 0ull;
        gemm512(acc, g_WT0, h0xT, K0TOT, wbuf, tid);   // h + x fused
        lstm_update(acc, sb0, c0T, h0xT, tid);         // h0 := out0[t]

#pragma unroll
        for (int i = 0; i < 32; i++) acc[i] = 0ull;
        gemm512(acc, g_WTih1, h0xT, HDIM, wbuf, tid);
        gemm512(acc, g_WThh1, h1T, HDIM, wbuf, tid);
        lstm_update(acc, sb1, c1T, h1T, tid);
    }

    // prev0 = x[:, -1, :3]
    if (tid < BB * NOUT) {
        int r = tid / NOUT, o = tid - r * NOUT;
        sprev[r * 4 + o] = un[r * (TSTEPS * NIN) + 14 * NIN + o];
    }
    __syncthreads();

    // ---- decoder ------------------------------------------------------------
    for (int s = 0; s < HOR; s++) {
        // dec_in = relu(prev @ Wp[:,:3]^T + embWp[s] + bp) -> h0xT rows 0..127
        {
            float4 wp = *(const float4*)(sWp3 + jj * 4);
            float base = sewp[s * HDIM + jj] + sbp[jj];
#pragma unroll
            for (int b = 0; b < 4; b++) {
                int r0 = b * 16 + r8 * 4;
                float v[4];
#pragma unroll
                for (int r = 0; r < 4; r++) {
                    float4 pv = *(const float4*)(sprev + (r0 + r) * 4);
                    v[r] = fmaxf(base + wp.x * pv.x + wp.y * pv.y + wp.z * pv.z, 0.f);
                }
                *(float4*)(h0xT + jj * STRH + r0) = make_float4(v[0], v[1], v[2], v[3]);
            }
        }

#pragma unroll
        for (int i = 0; i < 32; i++) acc[i] = 0ull;
        gemm512(acc, g_WTihd, h0xT, HDIM, wbuf, tid);
        gemm512(acc, g_WThhd, h1T, HDIM, wbuf, tid);
        lstm_update(acc, sbd, c1T, h1T, tid);
        __syncthreads();   // h1T visible for LN/head phase

        {   // LayerNorm + heads: 8 threads per row, 16 elems each
            int row = tid >> 3, sub = tid & 7;
            float hv[16];
#pragma unroll
            for (int q = 0; q < 16; q++) hv[q] = h1T[(sub * 16 + q) * STRH + row];
            float s1 = 0.f, s2 = 0.f;
#pragma unroll
            for (int q = 0; q < 16; q++) { s1 += hv[q]; s2 += hv[q] * hv[q]; }
#pragma unroll
            for (int d = 1; d < 8; d <<= 1) {
                s1 += __shfl_xor_sync(0xffffffffu, s1, d);
                s2 += __shfl_xor_sync(0xffffffffu, s2, d);
            }
            float mean = s1 * (1.f / 128.f);
            float var  = s2 * (1.f / 128.f) - mean * mean;
            float rstd = rsqrtf(var + 1e-5f);
            float m0 = 0, m1 = 0, m2 = 0, t0 = 0, t1 = 0, t2 = 0;
#pragma unroll
            for (int q = 0; q < 16; q++) {
                int j = sub * 16 + q;
                float f = (hv[q] - mean) * rstd * slng[j] + slnb[j];
                m0 += f * sWm[j];       m1 += f * sWm[128 + j]; m2 += f * sWm[256 + j];
                t0 += f * sWs[j];       t1 += f * sWs[128 + j]; t2 += f * sWs[256 + j];
            }
#pragma unroll
            for (int d = 1; d < 8; d <<= 1) {
                m0 += __shfl_xor_sync(0xffffffffu, m0, d);
                m1 += __shfl_xor_sync(0xffffffffu, m1, d);
                m2 += __shfl_xor_sync(0xffffffffu, m2, d);
                t0 += __shfl_xor_sync(0xffffffffu, t0, d);
                t1 += __shfl_xor_sync(0xffffffffu, t1, d);
                t2 += __shfl_xor_sync(0xffffffffu, t2, d);
            }
            if (sub == 0) {
                int gb = bbase + row;
                float mu0 = m0 + sbms[0], mu1 = m1 + sbms[1], mu2 = m2 + sbms[2];
                float l0 = fminf(fmaxf(t0 + sbms[4], -6.f), 3.f);
                float l1 = fminf(fmaxf(t1 + sbms[5], -6.f), 3.f);
                float l2 = fminf(fmaxf(t2 + sbms[6], -6.f), 3.f);
                size_t base = ((size_t)gb * HOR + s) * NOUT;
                out[base + 0] = mu0; out[base + 1] = mu1; out[base + 2] = mu2;
                float* outs = out + (size_t)NBATCH * HOR * NOUT;
                outs[base + 0] = l0; outs[base + 1] = l1; outs[base + 2] = l2;
                sprev[row * 4 + 0] = mu0; sprev[row * 4 + 1] = mu1; sprev[row * 4 + 2] = mu2;
            }
        }
        __syncthreads();   // sprev + LN reads done before next dec_in/h overwrite
    }
}

extern "C" void kernel_launch(void* const* d_in, const int* in_sizes, int n_in,
                              void* d_out, int out_size)
{
    const float* x    = (const float*)d_in[0];
    const float* Wih0 = (const float*)d_in[1];
    const float* Whh0 = (const float*)d_in[2];
    const float* b0   = (const float*)d_in[3];
    const float* Wih1 = (const float*)d_in[4];
    const float* Whh1 = (const float*)d_in[5];
    const float* b1   = (const float*)d_in[6];
    const float* Wihd = (const float*)d_in[7];
    const float* Whhd = (const float*)d_in[8];
    const float* bd   = (const float*)d_in[9];
    const float* emb  = (const float*)d_in[10];
    const float* Wp   = (const float*)d_in[11];
    const float* bp   = (const float*)d_in[12];
    const float* Wm   = (const float*)d_in[13];
    const float* bm   = (const float*)d_in[14];
    const float* Ws   = (const float*)d_in[15];
    const float* bs   = (const float*)d_in[16];
    const float* lng  = (const float*)d_in[17];
    const float* lnb  = (const float*)d_in[18];
    float* out = (float*)d_out;

    cudaFuncSetAttribute(traj_kernel, cudaFuncAttributeMaxDynamicSharedMemorySize, SMEM_BYTES);

    int prep_total = K0TOT * G4 + HDIM * G4 + HOR * HDIM + HDIM * 4;
    prep_kernel<<<(prep_total + 255) / 256, 256>>>(Wih0, Whh0, Wih1, Whh1, Wihd, Whhd, Wp, emb);

    traj_kernel<<<NBATCH / BB, NT, SMEM_BYTES>>>(x, b0, b1, bd, bp, Wm, bm, Ws, bs,
                                                 lng, lnb, out);
}